// round 7
// baseline (speedup 1.0000x reference)
#include <cuda_runtime.h>
#include <cuda_bf16.h>
#include <cstddef>

// ---------------------------------------------------------------------------
// Problem constants
// ---------------------------------------------------------------------------
static const int NPTS  = 65536;   // nodes
static const int HID   = 512;
static const int HH    = 1024;    // HEADS*HID
static const int KVSPL = 16;      // split-K factor for K^T V

// ---------------------------------------------------------------------------
// Scratch (device globals; no allocation allowed).  ~675 MB total.
// ---------------------------------------------------------------------------
__device__ float g_qk  [65536u * 1024u];      // K, later overwritten by Q (256MB)
__device__ float g_v   [65536u * 1024u];      // V; head-0 half later holds attn (256MB)
__device__ float g_h   [65536u * 512u];       // fc0 output (layer-0 prev)   (128MB)
__device__ float g_kvp [32u * 512u * 512u];   // split-K partials             (32MB)
__device__ float g_kvs [2u * 512u * 512u];    // K^T V per head               (2MB)
__device__ float g_ksp [64u * 1024u];
__device__ float g_ks  [1024u];
__device__ float g_red [8192u];
__device__ float g_scal[2u];
__device__ float g_inv [2u * 65536u];         // per-row per-head 1/denominator

// ---------------------------------------------------------------------------
// Helpers
// ---------------------------------------------------------------------------
__device__ __forceinline__ unsigned tf32_of(float f) {
    unsigned u;
    asm("cvt.rna.tf32.f32 %0, %1;" : "=r"(u) : "f"(f));
    return u;
}

__device__ __forceinline__ void mma_tf32(float c[4], const unsigned a[4],
                                         const unsigned b[2]) {
    asm volatile(
        "mma.sync.aligned.m16n8k8.row.col.f32.tf32.tf32.f32 "
        "{%0,%1,%2,%3},{%4,%5,%6,%7},{%8,%9},{%0,%1,%2,%3};\n"
        : "+f"(c[0]), "+f"(c[1]), "+f"(c[2]), "+f"(c[3])
        : "r"(a[0]), "r"(a[1]), "r"(a[2]), "r"(a[3]), "r"(b[0]), "r"(b[1]));
}

__device__ __forceinline__ float block_reduce_sum(float v, float* sm) {
    int tid = threadIdx.x;
    int lane = tid & 31, wid = tid >> 5;
    #pragma unroll
    for (int o = 16; o > 0; o >>= 1) v += __shfl_down_sync(0xffffffffu, v, o);
    __syncthreads();
    if (lane == 0) sm[wid] = v;
    __syncthreads();
    if (tid == 0) {
        float s = 0.f;
        #pragma unroll
        for (int i = 0; i < 8; i++) s += sm[i];
        sm[0] = s;
    }
    __syncthreads();
    return sm[0];
}

// ---------------------------------------------------------------------------
// TF32 tensor-core GEMM (NN): C[M,N] = A[M,K]*B[K,N] (+bias), row-major.
// 128x128 tile, BK=16, 256 threads (8 warps as 2x4), warp tile 64x32.
// Optionally emits per-block sum-of-squares of C into ss_out[block].
// Requires M%128==0, N%128==0, K%16==0.
// ---------------------------------------------------------------------------
__global__ __launch_bounds__(256) void gemm_nn_tf32(
    const float* __restrict__ A, const float* __restrict__ B,
    const float* __restrict__ bias, float* __restrict__ C,
    int M, int N, int K, int lda, int ldb, int ldc,
    float* __restrict__ ss_out)
{
    __shared__ unsigned As[128][20];   // [m][k]
    __shared__ unsigned Bs[16][136];   // [k][n]
    __shared__ float rsm[8];

    const int tid = threadIdx.x;
    const int lane = tid & 31;
    const int wid = tid >> 5;
    const int gid = lane >> 2, tig = lane & 3;
    const int warp_m = (wid >> 2) * 64;   // 0 or 64
    const int warp_n = (wid & 3) * 32;    // 0,32,64,96
    const int m0 = blockIdx.y * 128;
    const int n0 = blockIdx.x * 128;

    float acc[4][4][4];
    #pragma unroll
    for (int i = 0; i < 4; i++)
        #pragma unroll
        for (int j = 0; j < 4; j++)
            #pragma unroll
            for (int r = 0; r < 4; r++) acc[i][j][r] = 0.f;

    for (int k0 = 0; k0 < K; k0 += 16) {
        #pragma unroll
        for (int it = 0; it < 2; it++) {
            int idx = tid + it * 256;          // 0..511
            int arow = idx >> 2;               // 0..127
            int acol4 = (idx & 3) << 2;        // 0,4,8,12
            float4 a4 = *(const float4*)(A + (size_t)(m0 + arow) * lda + k0 + acol4);
            *(uint4*)&As[arow][acol4] =
                make_uint4(tf32_of(a4.x), tf32_of(a4.y), tf32_of(a4.z), tf32_of(a4.w));
        }
        #pragma unroll
        for (int it = 0; it < 2; it++) {
            int idx = tid + it * 256;
            int brow = idx >> 5;               // 0..15
            int bcol4 = (idx & 31) << 2;       // 0..124
            float4 b4 = *(const float4*)(B + (size_t)(k0 + brow) * ldb + n0 + bcol4);
            *(uint4*)&Bs[brow][bcol4] =
                make_uint4(tf32_of(b4.x), tf32_of(b4.y), tf32_of(b4.z), tf32_of(b4.w));
        }
        __syncthreads();

        #pragma unroll
        for (int kk = 0; kk < 16; kk += 8) {
            unsigned afr[4][4], bfr[4][2];
            #pragma unroll
            for (int i = 0; i < 4; i++) {
                int mm = warp_m + i * 16 + gid;
                afr[i][0] = As[mm][kk + tig];
                afr[i][1] = As[mm + 8][kk + tig];
                afr[i][2] = As[mm][kk + tig + 4];
                afr[i][3] = As[mm + 8][kk + tig + 4];
            }
            #pragma unroll
            for (int j = 0; j < 4; j++) {
                int nn = warp_n + j * 8 + gid;
                bfr[j][0] = Bs[kk + tig][nn];
                bfr[j][1] = Bs[kk + tig + 4][nn];
            }
            #pragma unroll
            for (int i = 0; i < 4; i++)
                #pragma unroll
                for (int j = 0; j < 4; j++) mma_tf32(acc[i][j], afr[i], bfr[j]);
        }
        __syncthreads();
    }

    float ss = 0.f;
    #pragma unroll
    for (int j = 0; j < 4; j++) {
        int c = n0 + warp_n + j * 8 + tig * 2;
        float bx = bias ? bias[c] : 0.f;
        float by = bias ? bias[c + 1] : 0.f;
        #pragma unroll
        for (int i = 0; i < 4; i++) {
            int r = m0 + warp_m + i * 16 + gid;
            float x0 = acc[i][j][0] + bx, x1 = acc[i][j][1] + by;
            float x2 = acc[i][j][2] + bx, x3 = acc[i][j][3] + by;
            *(float2*)(C + (size_t)r * ldc + c)       = make_float2(x0, x1);
            *(float2*)(C + (size_t)(r + 8) * ldc + c) = make_float2(x2, x3);
            ss += x0 * x0 + x1 * x1 + x2 * x2 + x3 * x3;
        }
    }
    if (ss_out) {
        float s = block_reduce_sum(ss, rsm);
        if (tid == 0) ss_out[blockIdx.y * gridDim.x + blockIdx.x] = s;
    }
}

// ---------------------------------------------------------------------------
// TF32 GEMM with fused attention epilogue:
//   C[r,c] (+)= 0.5 * inv[r] * ( (A@B)[r,c] * s  +  65536 * V[r,c] )
// A = Q head slice [65536,512] ld 1024, B = kvs head [512,512] ld 512,
// V ld 1024, C ld 1024.  beta=0: overwrite (head 0), beta=1: accumulate.
// Grid (4, 512). NOTE: for head 0, C aliases V elementwise (safe: per-element
// read-then-write by a single thread).
// ---------------------------------------------------------------------------
__global__ __launch_bounds__(256) void gemm_attn_tf32(
    const float* __restrict__ A, const float* __restrict__ B,
    const float* __restrict__ Vb, const float* __restrict__ invp,
    const float* __restrict__ scal, float* __restrict__ C, int beta)
{
    __shared__ unsigned As[128][20];
    __shared__ unsigned Bs[16][136];

    const int tid = threadIdx.x;
    const int lane = tid & 31;
    const int wid = tid >> 5;
    const int gid = lane >> 2, tig = lane & 3;
    const int warp_m = (wid >> 2) * 64;
    const int warp_n = (wid & 3) * 32;
    const int m0 = blockIdx.y * 128;
    const int n0 = blockIdx.x * 128;

    float acc[4][4][4];
    #pragma unroll
    for (int i = 0; i < 4; i++)
        #pragma unroll
        for (int j = 0; j < 4; j++)
            #pragma unroll
            for (int r = 0; r < 4; r++) acc[i][j][r] = 0.f;

    for (int k0 = 0; k0 < 512; k0 += 16) {
        #pragma unroll
        for (int it = 0; it < 2; it++) {
            int idx = tid + it * 256;
            int arow = idx >> 2;
            int acol4 = (idx & 3) << 2;
            float4 a4 = *(const float4*)(A + (size_t)(m0 + arow) * 1024 + k0 + acol4);
            *(uint4*)&As[arow][acol4] =
                make_uint4(tf32_of(a4.x), tf32_of(a4.y), tf32_of(a4.z), tf32_of(a4.w));
        }
        #pragma unroll
        for (int it = 0; it < 2; it++) {
            int idx = tid + it * 256;
            int brow = idx >> 5;
            int bcol4 = (idx & 31) << 2;
            float4 b4 = *(const float4*)(B + (size_t)(k0 + brow) * 512 + n0 + bcol4);
            *(uint4*)&Bs[brow][bcol4] =
                make_uint4(tf32_of(b4.x), tf32_of(b4.y), tf32_of(b4.z), tf32_of(b4.w));
        }
        __syncthreads();

        #pragma unroll
        for (int kk = 0; kk < 16; kk += 8) {
            unsigned afr[4][4], bfr[4][2];
            #pragma unroll
            for (int i = 0; i < 4; i++) {
                int mm = warp_m + i * 16 + gid;
                afr[i][0] = As[mm][kk + tig];
                afr[i][1] = As[mm + 8][kk + tig];
                afr[i][2] = As[mm][kk + tig + 4];
                afr[i][3] = As[mm + 8][kk + tig + 4];
            }
            #pragma unroll
            for (int j = 0; j < 4; j++) {
                int nn = warp_n + j * 8 + gid;
                bfr[j][0] = Bs[kk + tig][nn];
                bfr[j][1] = Bs[kk + tig + 4][nn];
            }
            #pragma unroll
            for (int i = 0; i < 4; i++)
                #pragma unroll
                for (int j = 0; j < 4; j++) mma_tf32(acc[i][j], afr[i], bfr[j]);
        }
        __syncthreads();
    }

    const float s = rsqrtf(scal[0] * scal[1]);   // 1/(||q||*||k||)
    #pragma unroll
    for (int j = 0; j < 4; j++) {
        int c = n0 + warp_n + j * 8 + tig * 2;
        #pragma unroll
        for (int i = 0; i < 4; i++) {
            int r = m0 + warp_m + i * 16 + gid;
            float iv0 = invp[2 * (size_t)r];
            float iv1 = invp[2 * (size_t)(r + 8)];
            float2 va = *(const float2*)(Vb + (size_t)r * 1024 + c);
            float2 vbv = *(const float2*)(Vb + (size_t)(r + 8) * 1024 + c);
            float x0 = (acc[i][j][0] * s + 65536.f * va.x)  * iv0 * 0.5f;
            float x1 = (acc[i][j][1] * s + 65536.f * va.y)  * iv0 * 0.5f;
            float x2 = (acc[i][j][2] * s + 65536.f * vbv.x) * iv1 * 0.5f;
            float x3 = (acc[i][j][3] * s + 65536.f * vbv.y) * iv1 * 0.5f;
            float* c0 = C + (size_t)r * 1024 + c;
            float* c1 = C + (size_t)(r + 8) * 1024 + c;
            if (beta) {
                float2 o0 = *(float2*)c0, o1 = *(float2*)c1;
                x0 += o0.x; x1 += o0.y; x2 += o1.x; x3 += o1.y;
            }
            *(float2*)c0 = make_float2(x0, x1);
            *(float2*)c1 = make_float2(x2, x3);
        }
    }
}

// ---------------------------------------------------------------------------
// TF32 tensor-core GEMM (TN) for kvs: C[m,d] = sum_l K[l,m]*V[l,d], split-K.
// grid (4, 4, z = h*16+split). Tile 128x128, BK=16.
// ---------------------------------------------------------------------------
__global__ __launch_bounds__(256) void gemm_tn_tf32_kv(
    const float* __restrict__ Kp, const float* __restrict__ Vp,
    float* __restrict__ part)
{
    __shared__ unsigned As[16][136];   // [l][m]
    __shared__ unsigned Bs[16][136];   // [l][d]

    const int tid = threadIdx.x;
    const int lane = tid & 31;
    const int wid = tid >> 5;
    const int gid = lane >> 2, tig = lane & 3;
    const int warp_m = (wid >> 2) * 64;
    const int warp_n = (wid & 3) * 32;
    const int d0 = blockIdx.x * 128;
    const int m0 = blockIdx.y * 128;
    const int h  = blockIdx.z >> 4;
    const int sp = blockIdx.z & 15;
    const int CH = NPTS / KVSPL;       // 4096

    const float* Ab = Kp + (size_t)h * 512;
    const float* Bb = Vp + (size_t)h * 512;

    float acc[4][4][4];
    #pragma unroll
    for (int i = 0; i < 4; i++)
        #pragma unroll
        for (int j = 0; j < 4; j++)
            #pragma unroll
            for (int r = 0; r < 4; r++) acc[i][j][r] = 0.f;

    const int lbeg = sp * CH, lend = lbeg + CH;
    for (int l0 = lbeg; l0 < lend; l0 += 16) {
        #pragma unroll
        for (int it = 0; it < 2; it++) {
            int idx = tid + it * 256;
            int lrow = idx >> 5;               // 0..15
            int col4 = (idx & 31) << 2;        // 0..124
            float4 a4 = *(const float4*)(Ab + (size_t)(l0 + lrow) * 1024 + m0 + col4);
            *(uint4*)&As[lrow][col4] =
                make_uint4(tf32_of(a4.x), tf32_of(a4.y), tf32_of(a4.z), tf32_of(a4.w));
            float4 b4 = *(const float4*)(Bb + (size_t)(l0 + lrow) * 1024 + d0 + col4);
            *(uint4*)&Bs[lrow][col4] =
                make_uint4(tf32_of(b4.x), tf32_of(b4.y), tf32_of(b4.z), tf32_of(b4.w));
        }
        __syncthreads();

        #pragma unroll
        for (int kk = 0; kk < 16; kk += 8) {
            unsigned afr[4][4], bfr[4][2];
            #pragma unroll
            for (int i = 0; i < 4; i++) {
                int mm = warp_m + i * 16 + gid;
                afr[i][0] = As[kk + tig][mm];
                afr[i][1] = As[kk + tig][mm + 8];
                afr[i][2] = As[kk + tig + 4][mm];
                afr[i][3] = As[kk + tig + 4][mm + 8];
            }
            #pragma unroll
            for (int j = 0; j < 4; j++) {
                int nn = warp_n + j * 8 + gid;
                bfr[j][0] = Bs[kk + tig][nn];
                bfr[j][1] = Bs[kk + tig + 4][nn];
            }
            #pragma unroll
            for (int i = 0; i < 4; i++)
                #pragma unroll
                for (int j = 0; j < 4; j++) mma_tf32(acc[i][j], afr[i], bfr[j]);
        }
        __syncthreads();
    }

    float* P = part + (size_t)blockIdx.z * 262144u;
    #pragma unroll
    for (int j = 0; j < 4; j++) {
        int c = d0 + warp_n + j * 8 + tig * 2;
        #pragma unroll
        for (int i = 0; i < 4; i++) {
            int r = m0 + warp_m + i * 16 + gid;
            *(float2*)(P + (size_t)r * 512 + c)       = make_float2(acc[i][j][0], acc[i][j][1]);
            *(float2*)(P + (size_t)(r + 8) * 512 + c) = make_float2(acc[i][j][2], acc[i][j][3]);
        }
    }
}

__global__ void kv_reduce(const float* __restrict__ part, float* __restrict__ kvs) {
    int idx = blockIdx.x * 256 + threadIdx.x;          // 0..524287
    int h = idx >> 18;
    int i = idx & 262143;
    const float* p = part + (size_t)(h * KVSPL) * 262144u + i;
    float s = 0.f;
    #pragma unroll
    for (int sp = 0; sp < KVSPL; sp++) s += p[(size_t)sp * 262144u];
    kvs[idx] = s;
}

// ---------------------------------------------------------------------------
// Deterministic scalar reduce of n partials
// ---------------------------------------------------------------------------
__global__ __launch_bounds__(256) void reduce_to_scalar(
    const float* __restrict__ part, int n, float* __restrict__ out)
{
    __shared__ float sm[8];
    float s = 0.f;
    for (int i = threadIdx.x; i < n; i += 256) s += part[i];
    s = block_reduce_sum(s, sm);
    if (threadIdx.x == 0) *out = s;
}

// ---------------------------------------------------------------------------
// ks_sum[c] = sum_l K[l, c]
// ---------------------------------------------------------------------------
__global__ __launch_bounds__(256) void kssum_kernel(
    const float* __restrict__ Kp, float* __restrict__ part)
{
    int col = blockIdx.y * 256 + threadIdx.x;   // grid.y = 4
    int l0 = blockIdx.x * 1024;                 // grid.x = 64
    float s = 0.f;
    for (int l = l0; l < l0 + 1024; l++) s += Kp[(size_t)l * 1024 + col];
    part[blockIdx.x * 1024 + col] = s;
}

__global__ __launch_bounds__(256) void kssum_reduce(
    const float* __restrict__ part, float* __restrict__ out)
{
    int col = blockIdx.x * 256 + threadIdx.x;   // grid = 4
    float s = 0.f;
    #pragma unroll
    for (int i = 0; i < 64; i++) s += part[i * 1024 + col];
    out[col] = s;
}

// ---------------------------------------------------------------------------
// Per-row attention denominators: inv[2n+h] = 1/(q_h . ks_h * s + 65536)
// ---------------------------------------------------------------------------
__global__ __launch_bounds__(256) void qd_inv(
    const float* __restrict__ q, const float* __restrict__ kss,
    const float* __restrict__ scal, float* __restrict__ inv)
{
    __shared__ float sm[8];
    int n = blockIdx.x, t = threadIdx.x;
    size_t r1 = (size_t)n * 1024;
    float s = rsqrtf(scal[0] * scal[1]);
    float qd0 = q[r1 + t] * kss[t] + q[r1 + 256 + t] * kss[256 + t];
    float qd1 = q[r1 + 512 + t] * kss[512 + t] + q[r1 + 768 + t] * kss[768 + t];
    qd0 = block_reduce_sum(qd0, sm);
    qd1 = block_reduce_sum(qd1, sm);
    if (t == 0) {
        inv[2 * n]     = 1.0f / (qd0 * s + 65536.0f);
        inv[2 * n + 1] = 1.0f / (qd1 * s + 65536.0f);
    }
}

// ---------------------------------------------------------------------------
// fc0 epilogue: LayerNorm + ReLU, one block per row
// ---------------------------------------------------------------------------
__global__ __launch_bounds__(256) void ln_relu(
    const float* __restrict__ x, const float* __restrict__ g,
    const float* __restrict__ b, float* __restrict__ out)
{
    __shared__ float sm[8];
    int n = blockIdx.x, t = threadIdx.x;
    size_t r = (size_t)n * 512;
    float v0 = x[r + t], v1 = x[r + 256 + t];
    float mu = block_reduce_sum(v0 + v1, sm) * (1.f / 512.f);
    float d0 = v0 - mu, d1 = v1 - mu;
    float var = block_reduce_sum(d0 * d0 + d1 * d1, sm) * (1.f / 512.f);
    float rs = rsqrtf(var + 1e-5f);
    float o0 = d0 * rs * g[t] + b[t];
    float o1 = d1 * rs * g[t + 256] + b[t + 256];
    out[r + t]       = fmaxf(o0, 0.f);
    out[r + 256 + t] = fmaxf(o1, 0.f);
}

// ---------------------------------------------------------------------------
// Residual + LayerNorm: out = LN(0.5*attn + 0.5*prev). attn has ld 1024.
// Safe when out aliases prev (row-local, read-before-write per thread).
// ---------------------------------------------------------------------------
__global__ __launch_bounds__(256) void combine_res_ln(
    const float* __restrict__ attn, const float* __restrict__ prev,
    const float* __restrict__ g, const float* __restrict__ b,
    float* __restrict__ out)
{
    __shared__ float sm[8];
    int n = blockIdx.x, t = threadIdx.x;
    size_t r1 = (size_t)n * 1024;
    size_t r5 = (size_t)n * 512;
    float val0 = 0.5f * attn[r1 + t]       + 0.5f * prev[r5 + t];
    float val1 = 0.5f * attn[r1 + 256 + t] + 0.5f * prev[r5 + 256 + t];
    float mu = block_reduce_sum(val0 + val1, sm) * (1.f / 512.f);
    float d0 = val0 - mu, d1 = val1 - mu;
    float var = block_reduce_sum(d0 * d0 + d1 * d1, sm) * (1.f / 512.f);
    float rs = rsqrtf(var + 1e-5f);
    out[r5 + t]       = d0 * rs * g[t] + b[t];
    out[r5 + 256 + t] = d1 * rs * g[t + 256] + b[t + 256];
}

// ---------------------------------------------------------------------------
// Launch
// ---------------------------------------------------------------------------
extern "C" void kernel_launch(void* const* d_in, const int* in_sizes, int n_in,
                              void* d_out, int out_size)
{
    (void)in_sizes; (void)n_in; (void)out_size;
    const float* x     = (const float*)d_in[0];
    const float* fc0_w = (const float*)d_in[1];
    const float* fc0_b = (const float*)d_in[2];
    const float* ln0_g = (const float*)d_in[3];
    const float* ln0_b = (const float*)d_in[4];
    const float* wq    = (const float*)d_in[5];
    const float* bq    = (const float*)d_in[6];
    const float* wk    = (const float*)d_in[7];
    const float* bk    = (const float*)d_in[8];
    const float* wv    = (const float*)d_in[9];
    const float* bv    = (const float*)d_in[10];
    const float* lng   = (const float*)d_in[11];
    const float* lnb   = (const float*)d_in[12];
    float* out = (float*)d_out;

    float *qk, *v, *hbuf, *kvp, *kvs, *ksp, *ks, *red, *scal, *inv;
    cudaGetSymbolAddress((void**)&qk,   g_qk);
    cudaGetSymbolAddress((void**)&v,    g_v);
    cudaGetSymbolAddress((void**)&hbuf, g_h);
    cudaGetSymbolAddress((void**)&kvp,  g_kvp);
    cudaGetSymbolAddress((void**)&kvs,  g_kvs);
    cudaGetSymbolAddress((void**)&ksp,  g_ksp);
    cudaGetSymbolAddress((void**)&ks,   g_ks);
    cudaGetSymbolAddress((void**)&red,  g_red);
    cudaGetSymbolAddress((void**)&scal, g_scal);
    cudaGetSymbolAddress((void**)&inv,  g_inv);

    dim3 thr(256);

    // --- input projection: h = relu(LN(x @ fc0_w + fc0_b)) ---
    gemm_nn_tf32<<<dim3(4, 512), thr>>>(x, fc0_w, fc0_b, v,
                                        NPTS, 512, 512, 512, 512, 512, nullptr);
    ln_relu<<<NPTS, thr>>>(v, ln0_g, ln0_b, hbuf);

    for (int L = 0; L < 2; L++) {
        const float* prev = L ? out : hbuf;
        float* lout = out;                       // layer 1 in-place (row-local)
        const float* WQ  = wq + (size_t)L * 512 * 1024;
        const float* WK  = wk + (size_t)L * 512 * 1024;
        const float* WV  = wv + (size_t)L * 512 * 1024;
        const float* BQ  = bq + (size_t)L * 1024;
        const float* BKb = bk + (size_t)L * 1024;
        const float* BV  = bv + (size_t)L * 1024;

        // V projection
        gemm_nn_tf32<<<dim3(8, 512), thr>>>(prev, WV, BV, v,
                                            NPTS, HH, HID, 512, 1024, 1024, nullptr);
        // K projection (+ sum-of-squares partials)
        gemm_nn_tf32<<<dim3(8, 512), thr>>>(prev, WK, BKb, qk,
                                            NPTS, HH, HID, 512, 1024, 1024, red + 4096);
        reduce_to_scalar<<<1, thr>>>(red + 4096, 4096, scal + 1);

        // ks_sum
        kssum_kernel<<<dim3(64, 4), thr>>>(qk, ksp);
        kssum_reduce<<<4, thr>>>(ksp, ks);

        // kvs = K^T V per head (split-K, deterministic)
        gemm_tn_tf32_kv<<<dim3(4, 4, 32), thr>>>(qk, v, kvp);
        kv_reduce<<<2048, thr>>>(kvp, kvs);

        // Q projection overwrites K (K is dead now) (+ ss partials)
        gemm_nn_tf32<<<dim3(8, 512), thr>>>(prev, WQ, BQ, qk,
                                            NPTS, HH, HID, 512, 1024, 1024, red);
        reduce_to_scalar<<<1, thr>>>(red, 4096, scal + 0);

        // per-row denominators
        qd_inv<<<NPTS, thr>>>(qk, ks, scal, inv);

        // fused Q@kvs + attention combine; attn aliases V's head-0 half
        gemm_attn_tf32<<<dim3(4, 512), thr>>>(qk, kvs, v, inv, scal, v, 0);
        gemm_attn_tf32<<<dim3(4, 512), thr>>>(qk + 512, kvs + 262144u,
                                              v + 512, inv + 1, scal, v, 1);

        // residual + LN
        combine_res_ln<<<NPTS, thr>>>(v, prev,
                                      lng + (size_t)L * 512, lnb + (size_t)L * 512,
                                      lout);
    }
}

// round 8
// speedup vs baseline: 1.1454x; 1.1454x over previous
#include <cuda_runtime.h>
#include <cuda_bf16.h>
#include <cstddef>

// ---------------------------------------------------------------------------
// Problem constants
// ---------------------------------------------------------------------------
static const int NPTS  = 65536;   // nodes
static const int HID   = 512;
static const int HH    = 1024;    // HEADS*HID
static const int KVSPL = 16;      // split-K factor for K^T V

// ---------------------------------------------------------------------------
// Scratch (device globals; no allocation allowed).  ~675 MB total.
// ---------------------------------------------------------------------------
__device__ float g_qk  [65536u * 1024u];      // K, later overwritten by Q (256MB)
__device__ float g_v   [65536u * 1024u];      // V; head-0 half later holds attn (256MB)
__device__ float g_h   [65536u * 512u];       // fc0 output (layer-0 prev)   (128MB)
__device__ float g_kvp [32u * 512u * 512u];   // split-K partials             (32MB)
__device__ float g_kvs [2u * 512u * 512u];    // K^T V per head               (2MB)
__device__ float g_ksp [64u * 1024u];
__device__ float g_ks  [1024u];
__device__ float g_red [8192u];
__device__ float g_scal[2u];
__device__ float g_inv [2u * 65536u];         // per-row per-head 1/denominator

// ---------------------------------------------------------------------------
// Helpers
// ---------------------------------------------------------------------------
__device__ __forceinline__ unsigned tf32_of(float f) {
    unsigned u;
    asm("cvt.rna.tf32.f32 %0, %1;" : "=r"(u) : "f"(f));
    return u;
}

__device__ __forceinline__ void mma_tf32(float c[4], const unsigned a[4],
                                         const unsigned b[2]) {
    asm volatile(
        "mma.sync.aligned.m16n8k8.row.col.f32.tf32.tf32.f32 "
        "{%0,%1,%2,%3},{%4,%5,%6,%7},{%8,%9},{%0,%1,%2,%3};\n"
        : "+f"(c[0]), "+f"(c[1]), "+f"(c[2]), "+f"(c[3])
        : "r"(a[0]), "r"(a[1]), "r"(a[2]), "r"(a[3]), "r"(b[0]), "r"(b[1]));
}

__device__ __forceinline__ float block_reduce_sum(float v, float* sm) {
    int tid = threadIdx.x;
    int lane = tid & 31, wid = tid >> 5;
    #pragma unroll
    for (int o = 16; o > 0; o >>= 1) v += __shfl_down_sync(0xffffffffu, v, o);
    __syncthreads();
    if (lane == 0) sm[wid] = v;
    __syncthreads();
    if (tid == 0) {
        float s = 0.f;
        #pragma unroll
        for (int i = 0; i < 8; i++) s += sm[i];
        sm[0] = s;
    }
    __syncthreads();
    return sm[0];
}

// ===========================================================================
// v2 GEMM core: block tile 128(M) x 256(N), BK=16, 256 threads.
// 8 warps as 2(M) x 4(N); warp tile 64x64 -> 4x8 m16n8k8 fragments.
// Compute/LDS-byte ratio 1.5x over 64x32 warp tile (smem-BW bound fix).
// Register-prefetch double buffering of the global->smem fill.
// ===========================================================================

// ---------------------------------------------------------------------------
// NN GEMM: C[M,N] = A[M,K]*B[K,N] (+bias), row-major, strided.
// Optionally emits per-block sum-of-squares of C into ss_out[block].
// Requires M%128==0, N%256==0, K%16==0.
// ---------------------------------------------------------------------------
__global__ __launch_bounds__(256) void gemm_nn_v2(
    const float* __restrict__ A, const float* __restrict__ B,
    const float* __restrict__ bias, float* __restrict__ C,
    int M, int N, int K, int lda, int ldb, int ldc,
    float* __restrict__ ss_out)
{
    __shared__ unsigned As[128][20];   // [m][k]; banks: 20*gid+tig -> all 32
    __shared__ unsigned Bs[16][264];   // [k][n]; banks: 8*tig+gid  -> all 32
    __shared__ float rsm[8];

    const int tid = threadIdx.x;
    const int lane = tid & 31;
    const int wid = tid >> 5;
    const int gid = lane >> 2, tig = lane & 3;
    const int warp_m = (wid & 1) * 64;    // 0 or 64
    const int warp_n = (wid >> 1) * 64;   // 0,64,128,192
    const int m0 = blockIdx.y * 128;
    const int n0 = blockIdx.x * 256;

    float acc[4][8][4];
    #pragma unroll
    for (int i = 0; i < 4; i++)
        #pragma unroll
        for (int j = 0; j < 8; j++)
            #pragma unroll
            for (int r = 0; r < 4; r++) acc[i][j][r] = 0.f;

    float4 pa[2], pb[4];
    // prologue: load tile k0=0 into registers
    #pragma unroll
    for (int it = 0; it < 2; it++) {
        int idx = tid + it * 256;              // 0..511
        int arow = idx >> 2, acol4 = (idx & 3) << 2;
        pa[it] = *(const float4*)(A + (size_t)(m0 + arow) * lda + acol4);
    }
    #pragma unroll
    for (int it = 0; it < 4; it++) {
        int idx = tid + it * 256;              // 0..1023
        int brow = idx >> 6, bcol4 = (idx & 63) << 2;
        pb[it] = *(const float4*)(B + (size_t)brow * ldb + n0 + bcol4);
    }

    for (int k0 = 0; k0 < K; k0 += 16) {
        // store current registers (with tf32 cvt) into smem
        #pragma unroll
        for (int it = 0; it < 2; it++) {
            int idx = tid + it * 256;
            int arow = idx >> 2, acol4 = (idx & 3) << 2;
            *(uint4*)&As[arow][acol4] = make_uint4(
                tf32_of(pa[it].x), tf32_of(pa[it].y),
                tf32_of(pa[it].z), tf32_of(pa[it].w));
        }
        #pragma unroll
        for (int it = 0; it < 4; it++) {
            int idx = tid + it * 256;
            int brow = idx >> 6, bcol4 = (idx & 63) << 2;
            *(uint4*)&Bs[brow][bcol4] = make_uint4(
                tf32_of(pb[it].x), tf32_of(pb[it].y),
                tf32_of(pb[it].z), tf32_of(pb[it].w));
        }
        __syncthreads();

        // prefetch next tile while computing
        if (k0 + 16 < K) {
            #pragma unroll
            for (int it = 0; it < 2; it++) {
                int idx = tid + it * 256;
                int arow = idx >> 2, acol4 = (idx & 3) << 2;
                pa[it] = *(const float4*)(A + (size_t)(m0 + arow) * lda + k0 + 16 + acol4);
            }
            #pragma unroll
            for (int it = 0; it < 4; it++) {
                int idx = tid + it * 256;
                int brow = idx >> 6, bcol4 = (idx & 63) << 2;
                pb[it] = *(const float4*)(B + (size_t)(k0 + 16 + brow) * ldb + n0 + bcol4);
            }
        }

        #pragma unroll
        for (int kk = 0; kk < 16; kk += 8) {
            unsigned afr[4][4], bfr[8][2];
            #pragma unroll
            for (int i = 0; i < 4; i++) {
                int mm = warp_m + i * 16 + gid;
                afr[i][0] = As[mm][kk + tig];
                afr[i][1] = As[mm + 8][kk + tig];
                afr[i][2] = As[mm][kk + tig + 4];
                afr[i][3] = As[mm + 8][kk + tig + 4];
            }
            #pragma unroll
            for (int j = 0; j < 8; j++) {
                int nn = warp_n + j * 8 + gid;
                bfr[j][0] = Bs[kk + tig][nn];
                bfr[j][1] = Bs[kk + tig + 4][nn];
            }
            #pragma unroll
            for (int i = 0; i < 4; i++)
                #pragma unroll
                for (int j = 0; j < 8; j++) mma_tf32(acc[i][j], afr[i], bfr[j]);
        }
        __syncthreads();
    }

    float ss = 0.f;
    #pragma unroll
    for (int j = 0; j < 8; j++) {
        int c = n0 + warp_n + j * 8 + tig * 2;
        float bx = bias ? bias[c] : 0.f;
        float by = bias ? bias[c + 1] : 0.f;
        #pragma unroll
        for (int i = 0; i < 4; i++) {
            int r = m0 + warp_m + i * 16 + gid;
            float x0 = acc[i][j][0] + bx, x1 = acc[i][j][1] + by;
            float x2 = acc[i][j][2] + bx, x3 = acc[i][j][3] + by;
            *(float2*)(C + (size_t)r * ldc + c)       = make_float2(x0, x1);
            *(float2*)(C + (size_t)(r + 8) * ldc + c) = make_float2(x2, x3);
            ss += x0 * x0 + x1 * x1 + x2 * x2 + x3 * x3;
        }
    }
    if (ss_out) {
        float s = block_reduce_sum(ss, rsm);
        if (tid == 0) ss_out[blockIdx.y * gridDim.x + blockIdx.x] = s;
    }
}

// ---------------------------------------------------------------------------
// Fused attention GEMM (v2 core):
//   C[r,c] (+)= 0.5 * inv[r] * ( (A@B)[r,c] * s  +  65536 * V[r,c] )
// A = Q head slice [65536,512] ld 1024, B = kvs head [512,512] ld 512,
// V ld 1024, C ld 1024.  beta=0: overwrite (head 0), beta=1: accumulate.
// Grid (2, 512). For head 0, C aliases V elementwise (single-thread r/w).
// ---------------------------------------------------------------------------
__global__ __launch_bounds__(256) void gemm_attn_v2(
    const float* __restrict__ A, const float* __restrict__ B,
    const float* __restrict__ Vb, const float* __restrict__ invp,
    const float* __restrict__ scal, float* __restrict__ C, int beta)
{
    __shared__ unsigned As[128][20];
    __shared__ unsigned Bs[16][264];

    const int tid = threadIdx.x;
    const int lane = tid & 31;
    const int wid = tid >> 5;
    const int gid = lane >> 2, tig = lane & 3;
    const int warp_m = (wid & 1) * 64;
    const int warp_n = (wid >> 1) * 64;
    const int m0 = blockIdx.y * 128;
    const int n0 = blockIdx.x * 256;

    float acc[4][8][4];
    #pragma unroll
    for (int i = 0; i < 4; i++)
        #pragma unroll
        for (int j = 0; j < 8; j++)
            #pragma unroll
            for (int r = 0; r < 4; r++) acc[i][j][r] = 0.f;

    float4 pa[2], pb[4];
    #pragma unroll
    for (int it = 0; it < 2; it++) {
        int idx = tid + it * 256;
        int arow = idx >> 2, acol4 = (idx & 3) << 2;
        pa[it] = *(const float4*)(A + (size_t)(m0 + arow) * 1024 + acol4);
    }
    #pragma unroll
    for (int it = 0; it < 4; it++) {
        int idx = tid + it * 256;
        int brow = idx >> 6, bcol4 = (idx & 63) << 2;
        pb[it] = *(const float4*)(B + (size_t)brow * 512 + n0 + bcol4);
    }

    for (int k0 = 0; k0 < 512; k0 += 16) {
        #pragma unroll
        for (int it = 0; it < 2; it++) {
            int idx = tid + it * 256;
            int arow = idx >> 2, acol4 = (idx & 3) << 2;
            *(uint4*)&As[arow][acol4] = make_uint4(
                tf32_of(pa[it].x), tf32_of(pa[it].y),
                tf32_of(pa[it].z), tf32_of(pa[it].w));
        }
        #pragma unroll
        for (int it = 0; it < 4; it++) {
            int idx = tid + it * 256;
            int brow = idx >> 6, bcol4 = (idx & 63) << 2;
            *(uint4*)&Bs[brow][bcol4] = make_uint4(
                tf32_of(pb[it].x), tf32_of(pb[it].y),
                tf32_of(pb[it].z), tf32_of(pb[it].w));
        }
        __syncthreads();

        if (k0 + 16 < 512) {
            #pragma unroll
            for (int it = 0; it < 2; it++) {
                int idx = tid + it * 256;
                int arow = idx >> 2, acol4 = (idx & 3) << 2;
                pa[it] = *(const float4*)(A + (size_t)(m0 + arow) * 1024 + k0 + 16 + acol4);
            }
            #pragma unroll
            for (int it = 0; it < 4; it++) {
                int idx = tid + it * 256;
                int brow = idx >> 6, bcol4 = (idx & 63) << 2;
                pb[it] = *(const float4*)(B + (size_t)(k0 + 16 + brow) * 512 + n0 + bcol4);
            }
        }

        #pragma unroll
        for (int kk = 0; kk < 16; kk += 8) {
            unsigned afr[4][4], bfr[8][2];
            #pragma unroll
            for (int i = 0; i < 4; i++) {
                int mm = warp_m + i * 16 + gid;
                afr[i][0] = As[mm][kk + tig];
                afr[i][1] = As[mm + 8][kk + tig];
                afr[i][2] = As[mm][kk + tig + 4];
                afr[i][3] = As[mm + 8][kk + tig + 4];
            }
            #pragma unroll
            for (int j = 0; j < 8; j++) {
                int nn = warp_n + j * 8 + gid;
                bfr[j][0] = Bs[kk + tig][nn];
                bfr[j][1] = Bs[kk + tig + 4][nn];
            }
            #pragma unroll
            for (int i = 0; i < 4; i++)
                #pragma unroll
                for (int j = 0; j < 8; j++) mma_tf32(acc[i][j], afr[i], bfr[j]);
        }
        __syncthreads();
    }

    const float s = rsqrtf(scal[0] * scal[1]);   // 1/(||q||*||k||)
    #pragma unroll
    for (int j = 0; j < 8; j++) {
        int c = n0 + warp_n + j * 8 + tig * 2;
        #pragma unroll
        for (int i = 0; i < 4; i++) {
            int r = m0 + warp_m + i * 16 + gid;
            float iv0 = invp[2 * (size_t)r];
            float iv1 = invp[2 * (size_t)(r + 8)];
            float2 va  = *(const float2*)(Vb + (size_t)r * 1024 + c);
            float2 vbv = *(const float2*)(Vb + (size_t)(r + 8) * 1024 + c);
            float x0 = (acc[i][j][0] * s + 65536.f * va.x)  * iv0 * 0.5f;
            float x1 = (acc[i][j][1] * s + 65536.f * va.y)  * iv0 * 0.5f;
            float x2 = (acc[i][j][2] * s + 65536.f * vbv.x) * iv1 * 0.5f;
            float x3 = (acc[i][j][3] * s + 65536.f * vbv.y) * iv1 * 0.5f;
            float* c0 = C + (size_t)r * 1024 + c;
            float* c1 = C + (size_t)(r + 8) * 1024 + c;
            if (beta) {
                float2 o0 = *(float2*)c0, o1 = *(float2*)c1;
                x0 += o0.x; x1 += o0.y; x2 += o1.x; x3 += o1.y;
            }
            *(float2*)c0 = make_float2(x0, x1);
            *(float2*)c1 = make_float2(x2, x3);
        }
    }
}

// ---------------------------------------------------------------------------
// TN GEMM for kvs (v2 core): C[m,d] = sum_l K[l,m]*V[l,d], split-K partials.
// Block tile 128(m) x 256(d); both smem tiles [l][col] = [16][264].
// grid (d/256=2, m/128=4, z = h*16+split).
// ---------------------------------------------------------------------------
__global__ __launch_bounds__(256) void gemm_tn_kv_v2(
    const float* __restrict__ Kp, const float* __restrict__ Vp,
    float* __restrict__ part)
{
    __shared__ unsigned As[16][264];   // [l][m]
    __shared__ unsigned Bs[16][264];   // [l][d]

    const int tid = threadIdx.x;
    const int lane = tid & 31;
    const int wid = tid >> 5;
    const int gid = lane >> 2, tig = lane & 3;
    const int warp_m = (wid & 1) * 64;
    const int warp_n = (wid >> 1) * 64;
    const int d0 = blockIdx.x * 256;
    const int m0 = blockIdx.y * 128;
    const int h  = blockIdx.z >> 4;
    const int sp = blockIdx.z & 15;
    const int CH = NPTS / KVSPL;       // 4096

    const float* Ab = Kp + (size_t)h * 512;
    const float* Bb = Vp + (size_t)h * 512;

    float acc[4][8][4];
    #pragma unroll
    for (int i = 0; i < 4; i++)
        #pragma unroll
        for (int j = 0; j < 8; j++)
            #pragma unroll
            for (int r = 0; r < 4; r++) acc[i][j][r] = 0.f;

    const int lbeg = sp * CH, lend = lbeg + CH;

    float4 pa[2], pb[4];
    #pragma unroll
    for (int it = 0; it < 2; it++) {
        int idx = tid + it * 256;              // 0..511
        int lrow = idx >> 5, mcol4 = (idx & 31) << 2;
        pa[it] = *(const float4*)(Ab + (size_t)(lbeg + lrow) * 1024 + m0 + mcol4);
    }
    #pragma unroll
    for (int it = 0; it < 4; it++) {
        int idx = tid + it * 256;              // 0..1023
        int lrow = idx >> 6, dcol4 = (idx & 63) << 2;
        pb[it] = *(const float4*)(Bb + (size_t)(lbeg + lrow) * 1024 + d0 + dcol4);
    }

    for (int l0 = lbeg; l0 < lend; l0 += 16) {
        #pragma unroll
        for (int it = 0; it < 2; it++) {
            int idx = tid + it * 256;
            int lrow = idx >> 5, mcol4 = (idx & 31) << 2;
            *(uint4*)&As[lrow][mcol4] = make_uint4(
                tf32_of(pa[it].x), tf32_of(pa[it].y),
                tf32_of(pa[it].z), tf32_of(pa[it].w));
        }
        #pragma unroll
        for (int it = 0; it < 4; it++) {
            int idx = tid + it * 256;
            int lrow = idx >> 6, dcol4 = (idx & 63) << 2;
            *(uint4*)&Bs[lrow][dcol4] = make_uint4(
                tf32_of(pb[it].x), tf32_of(pb[it].y),
                tf32_of(pb[it].z), tf32_of(pb[it].w));
        }
        __syncthreads();

        if (l0 + 16 < lend) {
            #pragma unroll
            for (int it = 0; it < 2; it++) {
                int idx = tid + it * 256;
                int lrow = idx >> 5, mcol4 = (idx & 31) << 2;
                pa[it] = *(const float4*)(Ab + (size_t)(l0 + 16 + lrow) * 1024 + m0 + mcol4);
            }
            #pragma unroll
            for (int it = 0; it < 4; it++) {
                int idx = tid + it * 256;
                int lrow = idx >> 6, dcol4 = (idx & 63) << 2;
                pb[it] = *(const float4*)(Bb + (size_t)(l0 + 16 + lrow) * 1024 + d0 + dcol4);
            }
        }

        #pragma unroll
        for (int kk = 0; kk < 16; kk += 8) {
            unsigned afr[4][4], bfr[8][2];
            #pragma unroll
            for (int i = 0; i < 4; i++) {
                int mm = warp_m + i * 16 + gid;
                afr[i][0] = As[kk + tig][mm];
                afr[i][1] = As[kk + tig][mm + 8];
                afr[i][2] = As[kk + tig + 4][mm];
                afr[i][3] = As[kk + tig + 4][mm + 8];
            }
            #pragma unroll
            for (int j = 0; j < 8; j++) {
                int nn = warp_n + j * 8 + gid;
                bfr[j][0] = Bs[kk + tig][nn];
                bfr[j][1] = Bs[kk + tig + 4][nn];
            }
            #pragma unroll
            for (int i = 0; i < 4; i++)
                #pragma unroll
                for (int j = 0; j < 8; j++) mma_tf32(acc[i][j], afr[i], bfr[j]);
        }
        __syncthreads();
    }

    float* P = part + (size_t)blockIdx.z * 262144u;
    #pragma unroll
    for (int j = 0; j < 8; j++) {
        int c = d0 + warp_n + j * 8 + tig * 2;
        #pragma unroll
        for (int i = 0; i < 4; i++) {
            int r = m0 + warp_m + i * 16 + gid;
            *(float2*)(P + (size_t)r * 512 + c)       = make_float2(acc[i][j][0], acc[i][j][1]);
            *(float2*)(P + (size_t)(r + 8) * 512 + c) = make_float2(acc[i][j][2], acc[i][j][3]);
        }
    }
}

__global__ void kv_reduce(const float* __restrict__ part, float* __restrict__ kvs) {
    int idx = blockIdx.x * 256 + threadIdx.x;          // 0..524287
    int h = idx >> 18;
    int i = idx & 262143;
    const float* p = part + (size_t)(h * KVSPL) * 262144u + i;
    float s = 0.f;
    #pragma unroll
    for (int sp = 0; sp < KVSPL; sp++) s += p[(size_t)sp * 262144u];
    kvs[idx] = s;
}

// ---------------------------------------------------------------------------
// Deterministic scalar reduce of n partials
// ---------------------------------------------------------------------------
__global__ __launch_bounds__(256) void reduce_to_scalar(
    const float* __restrict__ part, int n, float* __restrict__ out)
{
    __shared__ float sm[8];
    float s = 0.f;
    for (int i = threadIdx.x; i < n; i += 256) s += part[i];
    s = block_reduce_sum(s, sm);
    if (threadIdx.x == 0) *out = s;
}

// ---------------------------------------------------------------------------
// ks_sum[c] = sum_l K[l, c]
// ---------------------------------------------------------------------------
__global__ __launch_bounds__(256) void kssum_kernel(
    const float* __restrict__ Kp, float* __restrict__ part)
{
    int col = blockIdx.y * 256 + threadIdx.x;   // grid.y = 4
    int l0 = blockIdx.x * 1024;                 // grid.x = 64
    float s = 0.f;
    for (int l = l0; l < l0 + 1024; l++) s += Kp[(size_t)l * 1024 + col];
    part[blockIdx.x * 1024 + col] = s;
}

__global__ __launch_bounds__(256) void kssum_reduce(
    const float* __restrict__ part, float* __restrict__ out)
{
    int col = blockIdx.x * 256 + threadIdx.x;   // grid = 4
    float s = 0.f;
    #pragma unroll
    for (int i = 0; i < 64; i++) s += part[i * 1024 + col];
    out[col] = s;
}

// ---------------------------------------------------------------------------
// Per-row attention denominators: inv[2n+h] = 1/(q_h . ks_h * s + 65536)
// ---------------------------------------------------------------------------
__global__ __launch_bounds__(256) void qd_inv(
    const float* __restrict__ q, const float* __restrict__ kss,
    const float* __restrict__ scal, float* __restrict__ inv)
{
    __shared__ float sm[8];
    int n = blockIdx.x, t = threadIdx.x;
    size_t r1 = (size_t)n * 1024;
    float s = rsqrtf(scal[0] * scal[1]);
    float qd0 = q[r1 + t] * kss[t] + q[r1 + 256 + t] * kss[256 + t];
    float qd1 = q[r1 + 512 + t] * kss[512 + t] + q[r1 + 768 + t] * kss[768 + t];
    qd0 = block_reduce_sum(qd0, sm);
    qd1 = block_reduce_sum(qd1, sm);
    if (t == 0) {
        inv[2 * n]     = 1.0f / (qd0 * s + 65536.0f);
        inv[2 * n + 1] = 1.0f / (qd1 * s + 65536.0f);
    }
}

// ---------------------------------------------------------------------------
// fc0 epilogue: LayerNorm + ReLU, one block per row
// ---------------------------------------------------------------------------
__global__ __launch_bounds__(256) void ln_relu(
    const float* __restrict__ x, const float* __restrict__ g,
    const float* __restrict__ b, float* __restrict__ out)
{
    __shared__ float sm[8];
    int n = blockIdx.x, t = threadIdx.x;
    size_t r = (size_t)n * 512;
    float v0 = x[r + t], v1 = x[r + 256 + t];
    float mu = block_reduce_sum(v0 + v1, sm) * (1.f / 512.f);
    float d0 = v0 - mu, d1 = v1 - mu;
    float var = block_reduce_sum(d0 * d0 + d1 * d1, sm) * (1.f / 512.f);
    float rs = rsqrtf(var + 1e-5f);
    float o0 = d0 * rs * g[t] + b[t];
    float o1 = d1 * rs * g[t + 256] + b[t + 256];
    out[r + t]       = fmaxf(o0, 0.f);
    out[r + 256 + t] = fmaxf(o1, 0.f);
}

// ---------------------------------------------------------------------------
// Residual + LayerNorm: out = LN(0.5*attn + 0.5*prev). attn has ld 1024.
// Safe when out aliases prev (row-local, read-before-write per thread).
// ---------------------------------------------------------------------------
__global__ __launch_bounds__(256) void combine_res_ln(
    const float* __restrict__ attn, const float* __restrict__ prev,
    const float* __restrict__ g, const float* __restrict__ b,
    float* __restrict__ out)
{
    __shared__ float sm[8];
    int n = blockIdx.x, t = threadIdx.x;
    size_t r1 = (size_t)n * 1024;
    size_t r5 = (size_t)n * 512;
    float val0 = 0.5f * attn[r1 + t]       + 0.5f * prev[r5 + t];
    float val1 = 0.5f * attn[r1 + 256 + t] + 0.5f * prev[r5 + 256 + t];
    float mu = block_reduce_sum(val0 + val1, sm) * (1.f / 512.f);
    float d0 = val0 - mu, d1 = val1 - mu;
    float var = block_reduce_sum(d0 * d0 + d1 * d1, sm) * (1.f / 512.f);
    float rs = rsqrtf(var + 1e-5f);
    out[r5 + t]       = d0 * rs * g[t] + b[t];
    out[r5 + 256 + t] = d1 * rs * g[t + 256] + b[t + 256];
}

// ---------------------------------------------------------------------------
// Launch
// ---------------------------------------------------------------------------
extern "C" void kernel_launch(void* const* d_in, const int* in_sizes, int n_in,
                              void* d_out, int out_size)
{
    (void)in_sizes; (void)n_in; (void)out_size;
    const float* x     = (const float*)d_in[0];
    const float* fc0_w = (const float*)d_in[1];
    const float* fc0_b = (const float*)d_in[2];
    const float* ln0_g = (const float*)d_in[3];
    const float* ln0_b = (const float*)d_in[4];
    const float* wq    = (const float*)d_in[5];
    const float* bq    = (const float*)d_in[6];
    const float* wk    = (const float*)d_in[7];
    const float* bk    = (const float*)d_in[8];
    const float* wv    = (const float*)d_in[9];
    const float* bv    = (const float*)d_in[10];
    const float* lng   = (const float*)d_in[11];
    const float* lnb   = (const float*)d_in[12];
    float* out = (float*)d_out;

    float *qk, *v, *hbuf, *kvp, *kvs, *ksp, *ks, *red, *scal, *inv;
    cudaGetSymbolAddress((void**)&qk,   g_qk);
    cudaGetSymbolAddress((void**)&v,    g_v);
    cudaGetSymbolAddress((void**)&hbuf, g_h);
    cudaGetSymbolAddress((void**)&kvp,  g_kvp);
    cudaGetSymbolAddress((void**)&kvs,  g_kvs);
    cudaGetSymbolAddress((void**)&ksp,  g_ksp);
    cudaGetSymbolAddress((void**)&ks,   g_ks);
    cudaGetSymbolAddress((void**)&red,  g_red);
    cudaGetSymbolAddress((void**)&scal, g_scal);
    cudaGetSymbolAddress((void**)&inv,  g_inv);

    dim3 thr(256);

    // --- input projection: h = relu(LN(x @ fc0_w + fc0_b)) ---
    gemm_nn_v2<<<dim3(2, 512), thr>>>(x, fc0_w, fc0_b, v,
                                      NPTS, 512, 512, 512, 512, 512, nullptr);
    ln_relu<<<NPTS, thr>>>(v, ln0_g, ln0_b, hbuf);

    for (int L = 0; L < 2; L++) {
        const float* prev = L ? out : hbuf;
        float* lout = out;                       // layer 1 in-place (row-local)
        const float* WQ  = wq + (size_t)L * 512 * 1024;
        const float* WK  = wk + (size_t)L * 512 * 1024;
        const float* WV  = wv + (size_t)L * 512 * 1024;
        const float* BQ  = bq + (size_t)L * 1024;
        const float* BKb = bk + (size_t)L * 1024;
        const float* BV  = bv + (size_t)L * 1024;

        // V projection
        gemm_nn_v2<<<dim3(4, 512), thr>>>(prev, WV, BV, v,
                                          NPTS, HH, HID, 512, 1024, 1024, nullptr);
        // K projection (+ sum-of-squares partials)
        gemm_nn_v2<<<dim3(4, 512), thr>>>(prev, WK, BKb, qk,
                                          NPTS, HH, HID, 512, 1024, 1024, red + 4096);
        reduce_to_scalar<<<1, thr>>>(red + 4096, 2048, scal + 1);

        // ks_sum
        kssum_kernel<<<dim3(64, 4), thr>>>(qk, ksp);
        kssum_reduce<<<4, thr>>>(ksp, ks);

        // kvs = K^T V per head (split-K, deterministic)
        gemm_tn_kv_v2<<<dim3(2, 4, 32), thr>>>(qk, v, kvp);
        kv_reduce<<<2048, thr>>>(kvp, kvs);

        // Q projection overwrites K (K is dead now) (+ ss partials)
        gemm_nn_v2<<<dim3(4, 512), thr>>>(prev, WQ, BQ, qk,
                                          NPTS, HH, HID, 512, 1024, 1024, red);
        reduce_to_scalar<<<1, thr>>>(red, 2048, scal + 0);

        // per-row denominators
        qd_inv<<<NPTS, thr>>>(qk, ks, scal, inv);

        // fused Q@kvs + attention combine; attn aliases V's head-0 half
        gemm_attn_v2<<<dim3(2, 512), thr>>>(qk, kvs, v, inv, scal, v, 0);
        gemm_attn_v2<<<dim3(2, 512), thr>>>(qk + 512, kvs + 262144u,
                                            v + 512, inv + 1, scal, v, 1);

        // residual + LN
        combine_res_ln<<<NPTS, thr>>>(v, prev,
                                      lng + (size_t)L * 512, lnb + (size_t)L * 512,
                                      lout);
    }
}

// round 9
// speedup vs baseline: 1.1845x; 1.0342x over previous
#include <cuda_runtime.h>
#include <cuda_bf16.h>
#include <cstddef>

// ---------------------------------------------------------------------------
// Problem constants
// ---------------------------------------------------------------------------
static const int NPTS  = 65536;   // nodes
static const int HID   = 512;
static const int HH    = 1024;    // HEADS*HID
static const int KVSPL = 16;      // split-K factor for K^T V

// ---------------------------------------------------------------------------
// Scratch (device globals; no allocation allowed).
// ---------------------------------------------------------------------------
__device__ float g_qk  [65536u * 1024u];      // K, later overwritten by Q (256MB)
__device__ float g_v   [65536u * 1024u];      // V; head-0 half later holds attn (256MB)
__device__ float g_h   [65536u * 512u];       // fc0 output (layer-0 prev)   (128MB)
__device__ float g_kvp [32u * 512u * 512u];   // split-K partials             (32MB)
__device__ float g_kvs [2u * 512u * 512u];    // K^T V per head               (2MB)
__device__ float g_ksp [512u * 1024u];        // per-block column-sum partials (2MB)
__device__ float g_ks  [1024u];
__device__ float g_red [8192u];
__device__ float g_scal[2u];
__device__ float g_qdp [4u * 65536u];         // per-ntile q.ks row partials  (1MB)
__device__ float g_inv [2u * 65536u];         // per-row per-head 1/denominator

// ---------------------------------------------------------------------------
// Helpers
// ---------------------------------------------------------------------------
__device__ __forceinline__ unsigned tf32_of(float f) {
    unsigned u;
    asm("cvt.rna.tf32.f32 %0, %1;" : "=r"(u) : "f"(f));
    return u;
}

__device__ __forceinline__ void mma_tf32(float c[4], const unsigned a[4],
                                         const unsigned b[2]) {
    asm volatile(
        "mma.sync.aligned.m16n8k8.row.col.f32.tf32.tf32.f32 "
        "{%0,%1,%2,%3},{%4,%5,%6,%7},{%8,%9},{%0,%1,%2,%3};\n"
        : "+f"(c[0]), "+f"(c[1]), "+f"(c[2]), "+f"(c[3])
        : "r"(a[0]), "r"(a[1]), "r"(a[2]), "r"(a[3]), "r"(b[0]), "r"(b[1]));
}

__device__ __forceinline__ float block_reduce_sum(float v, float* sm) {
    int tid = threadIdx.x;
    int lane = tid & 31, wid = tid >> 5;
    #pragma unroll
    for (int o = 16; o > 0; o >>= 1) v += __shfl_down_sync(0xffffffffu, v, o);
    __syncthreads();
    if (lane == 0) sm[wid] = v;
    __syncthreads();
    if (tid == 0) {
        float s = 0.f;
        #pragma unroll
        for (int i = 0; i < 8; i++) s += sm[i];
        sm[0] = s;
    }
    __syncthreads();
    return sm[0];
}

// ===========================================================================
// v2 GEMM core: block tile 128(M) x 256(N), BK=16, 256 threads.
// 8 warps as 2(M) x 4(N); warp tile 64x64 -> 4x8 m16n8k8 fragments.
// Fused epilogue options:
//   ss_out     : per-block sum-of-squares of C
//   colsum_out : per-block column sums of C  (ks_sum fusion, K projection)
//   ksvec+qdp  : per-block row sums of C[r,c]*ks[c]  (q.ks fusion, Q proj)
// ===========================================================================
__global__ __launch_bounds__(256) void gemm_nn_v2(
    const float* __restrict__ A, const float* __restrict__ B,
    const float* __restrict__ bias, float* __restrict__ C,
    int M, int N, int K, int lda, int ldb, int ldc,
    float* __restrict__ ss_out,
    float* __restrict__ colsum_out,
    const float* __restrict__ ksvec,
    float* __restrict__ qdp_out)
{
    __shared__ unsigned As[128][20];   // [m][k]
    __shared__ unsigned Bs[16][264];   // [k][n]
    __shared__ float epism[4096];      // union: colsum (256*8*2) / qd (256*4*2)
    __shared__ float rsm[8];

    const int tid = threadIdx.x;
    const int lane = tid & 31;
    const int wid = tid >> 5;
    const int gid = lane >> 2, tig = lane & 3;
    const int warp_m = (wid & 1) * 64;    // 0 or 64
    const int warp_n = (wid >> 1) * 64;   // 0,64,128,192
    const int m0 = blockIdx.y * 128;
    const int n0 = blockIdx.x * 256;

    float acc[4][8][4];
    #pragma unroll
    for (int i = 0; i < 4; i++)
        #pragma unroll
        for (int j = 0; j < 8; j++)
            #pragma unroll
            for (int r = 0; r < 4; r++) acc[i][j][r] = 0.f;

    float4 pa[2], pb[4];
    #pragma unroll
    for (int it = 0; it < 2; it++) {
        int idx = tid + it * 256;
        int arow = idx >> 2, acol4 = (idx & 3) << 2;
        pa[it] = *(const float4*)(A + (size_t)(m0 + arow) * lda + acol4);
    }
    #pragma unroll
    for (int it = 0; it < 4; it++) {
        int idx = tid + it * 256;
        int brow = idx >> 6, bcol4 = (idx & 63) << 2;
        pb[it] = *(const float4*)(B + (size_t)brow * ldb + n0 + bcol4);
    }

    for (int k0 = 0; k0 < K; k0 += 16) {
        #pragma unroll
        for (int it = 0; it < 2; it++) {
            int idx = tid + it * 256;
            int arow = idx >> 2, acol4 = (idx & 3) << 2;
            *(uint4*)&As[arow][acol4] = make_uint4(
                tf32_of(pa[it].x), tf32_of(pa[it].y),
                tf32_of(pa[it].z), tf32_of(pa[it].w));
        }
        #pragma unroll
        for (int it = 0; it < 4; it++) {
            int idx = tid + it * 256;
            int brow = idx >> 6, bcol4 = (idx & 63) << 2;
            *(uint4*)&Bs[brow][bcol4] = make_uint4(
                tf32_of(pb[it].x), tf32_of(pb[it].y),
                tf32_of(pb[it].z), tf32_of(pb[it].w));
        }
        __syncthreads();

        if (k0 + 16 < K) {
            #pragma unroll
            for (int it = 0; it < 2; it++) {
                int idx = tid + it * 256;
                int arow = idx >> 2, acol4 = (idx & 3) << 2;
                pa[it] = *(const float4*)(A + (size_t)(m0 + arow) * lda + k0 + 16 + acol4);
            }
            #pragma unroll
            for (int it = 0; it < 4; it++) {
                int idx = tid + it * 256;
                int brow = idx >> 6, bcol4 = (idx & 63) << 2;
                pb[it] = *(const float4*)(B + (size_t)(k0 + 16 + brow) * ldb + n0 + bcol4);
            }
        }

        #pragma unroll
        for (int kk = 0; kk < 16; kk += 8) {
            unsigned afr[4][4], bfr[8][2];
            #pragma unroll
            for (int i = 0; i < 4; i++) {
                int mm = warp_m + i * 16 + gid;
                afr[i][0] = As[mm][kk + tig];
                afr[i][1] = As[mm + 8][kk + tig];
                afr[i][2] = As[mm][kk + tig + 4];
                afr[i][3] = As[mm + 8][kk + tig + 4];
            }
            #pragma unroll
            for (int j = 0; j < 8; j++) {
                int nn = warp_n + j * 8 + gid;
                bfr[j][0] = Bs[kk + tig][nn];
                bfr[j][1] = Bs[kk + tig + 4][nn];
            }
            #pragma unroll
            for (int i = 0; i < 4; i++)
                #pragma unroll
                for (int j = 0; j < 8; j++) mma_tf32(acc[i][j], afr[i], bfr[j]);
        }
        __syncthreads();
    }

    // ---- epilogue: bias add, store, fused reductions ----
    const bool do_cs = (colsum_out != nullptr);
    const bool do_qd = (qdp_out != nullptr);
    float ss = 0.f;
    float qd[4][2];
    #pragma unroll
    for (int i = 0; i < 4; i++) { qd[i][0] = 0.f; qd[i][1] = 0.f; }

    #pragma unroll
    for (int j = 0; j < 8; j++) {
        int c = n0 + warp_n + j * 8 + tig * 2;
        float bx = bias ? bias[c] : 0.f;
        float by = bias ? bias[c + 1] : 0.f;
        float ks0 = 0.f, ks1 = 0.f;
        if (do_qd) { ks0 = ksvec[c]; ks1 = ksvec[c + 1]; }
        float cs0 = 0.f, cs1 = 0.f;
        #pragma unroll
        for (int i = 0; i < 4; i++) {
            int r = m0 + warp_m + i * 16 + gid;
            float x0 = acc[i][j][0] + bx, x1 = acc[i][j][1] + by;
            float x2 = acc[i][j][2] + bx, x3 = acc[i][j][3] + by;
            *(float2*)(C + (size_t)r * ldc + c)       = make_float2(x0, x1);
            *(float2*)(C + (size_t)(r + 8) * ldc + c) = make_float2(x2, x3);
            ss += x0 * x0 + x1 * x1 + x2 * x2 + x3 * x3;
            cs0 += x0 + x2; cs1 += x1 + x3;
            qd[i][0] += x0 * ks0 + x1 * ks1;
            qd[i][1] += x2 * ks0 + x3 * ks1;
        }
        if (do_cs) {
            epism[(tid * 8 + j) * 2 + 0] = cs0;
            epism[(tid * 8 + j) * 2 + 1] = cs1;
        }
    }

    if (do_cs) {
        __syncthreads();
        // thread t handles column t of this block's 256 columns
        int c = tid;
        int wn = c >> 6, j = (c >> 3) & 7, tg = (c & 7) >> 1, e = c & 1;
        float s = 0.f;
        #pragma unroll
        for (int wm = 0; wm < 2; wm++)
            #pragma unroll
            for (int g = 0; g < 8; g++) {
                int t2 = (2 * wn + wm) * 32 + g * 4 + tg;
                s += epism[(t2 * 8 + j) * 2 + e];
            }
        colsum_out[(size_t)blockIdx.y * 1024 + n0 + c] = s;
    }

    if (do_qd) {
        __syncthreads();
        #pragma unroll
        for (int i = 0; i < 4; i++) {
            epism[(tid * 4 + i) * 2 + 0] = qd[i][0];
            epism[(tid * 4 + i) * 2 + 1] = qd[i][1];
        }
        __syncthreads();
        if (tid < 128) {
            int rl = tid;
            int wm = rl >> 6, rem = rl & 63;
            int i = rem >> 4, hf = (rem >> 3) & 1, g = rem & 7;
            float s = 0.f;
            #pragma unroll
            for (int wn = 0; wn < 4; wn++)
                #pragma unroll
                for (int tg = 0; tg < 4; tg++) {
                    int t2 = (2 * wn + wm) * 32 + g * 4 + tg;
                    s += epism[(t2 * 4 + i) * 2 + hf];
                }
            qdp_out[(size_t)blockIdx.x * 65536u + m0 + rl] = s;
        }
    }

    if (ss_out) {
        float s = block_reduce_sum(ss, rsm);
        if (tid == 0) ss_out[blockIdx.y * gridDim.x + blockIdx.x] = s;
    }
}

// ---------------------------------------------------------------------------
// Fused attention GEMM (v2 core):
//   C[r,c] (+)= 0.5 * inv[r] * ( (A@B)[r,c] * s  +  65536 * V[r,c] )
// ---------------------------------------------------------------------------
__global__ __launch_bounds__(256) void gemm_attn_v2(
    const float* __restrict__ A, const float* __restrict__ B,
    const float* __restrict__ Vb, const float* __restrict__ invp,
    const float* __restrict__ scal, float* __restrict__ C, int beta)
{
    __shared__ unsigned As[128][20];
    __shared__ unsigned Bs[16][264];

    const int tid = threadIdx.x;
    const int lane = tid & 31;
    const int wid = tid >> 5;
    const int gid = lane >> 2, tig = lane & 3;
    const int warp_m = (wid & 1) * 64;
    const int warp_n = (wid >> 1) * 64;
    const int m0 = blockIdx.y * 128;
    const int n0 = blockIdx.x * 256;

    float acc[4][8][4];
    #pragma unroll
    for (int i = 0; i < 4; i++)
        #pragma unroll
        for (int j = 0; j < 8; j++)
            #pragma unroll
            for (int r = 0; r < 4; r++) acc[i][j][r] = 0.f;

    float4 pa[2], pb[4];
    #pragma unroll
    for (int it = 0; it < 2; it++) {
        int idx = tid + it * 256;
        int arow = idx >> 2, acol4 = (idx & 3) << 2;
        pa[it] = *(const float4*)(A + (size_t)(m0 + arow) * 1024 + acol4);
    }
    #pragma unroll
    for (int it = 0; it < 4; it++) {
        int idx = tid + it * 256;
        int brow = idx >> 6, bcol4 = (idx & 63) << 2;
        pb[it] = *(const float4*)(B + (size_t)brow * 512 + n0 + bcol4);
    }

    for (int k0 = 0; k0 < 512; k0 += 16) {
        #pragma unroll
        for (int it = 0; it < 2; it++) {
            int idx = tid + it * 256;
            int arow = idx >> 2, acol4 = (idx & 3) << 2;
            *(uint4*)&As[arow][acol4] = make_uint4(
                tf32_of(pa[it].x), tf32_of(pa[it].y),
                tf32_of(pa[it].z), tf32_of(pa[it].w));
        }
        #pragma unroll
        for (int it = 0; it < 4; it++) {
            int idx = tid + it * 256;
            int brow = idx >> 6, bcol4 = (idx & 63) << 2;
            *(uint4*)&Bs[brow][bcol4] = make_uint4(
                tf32_of(pb[it].x), tf32_of(pb[it].y),
                tf32_of(pb[it].z), tf32_of(pb[it].w));
        }
        __syncthreads();

        if (k0 + 16 < 512) {
            #pragma unroll
            for (int it = 0; it < 2; it++) {
                int idx = tid + it * 256;
                int arow = idx >> 2, acol4 = (idx & 3) << 2;
                pa[it] = *(const float4*)(A + (size_t)(m0 + arow) * 1024 + k0 + 16 + acol4);
            }
            #pragma unroll
            for (int it = 0; it < 4; it++) {
                int idx = tid + it * 256;
                int brow = idx >> 6, bcol4 = (idx & 63) << 2;
                pb[it] = *(const float4*)(B + (size_t)(k0 + 16 + brow) * 512 + n0 + bcol4);
            }
        }

        #pragma unroll
        for (int kk = 0; kk < 16; kk += 8) {
            unsigned afr[4][4], bfr[8][2];
            #pragma unroll
            for (int i = 0; i < 4; i++) {
                int mm = warp_m + i * 16 + gid;
                afr[i][0] = As[mm][kk + tig];
                afr[i][1] = As[mm + 8][kk + tig];
                afr[i][2] = As[mm][kk + tig + 4];
                afr[i][3] = As[mm + 8][kk + tig + 4];
            }
            #pragma unroll
            for (int j = 0; j < 8; j++) {
                int nn = warp_n + j * 8 + gid;
                bfr[j][0] = Bs[kk + tig][nn];
                bfr[j][1] = Bs[kk + tig + 4][nn];
            }
            #pragma unroll
            for (int i = 0; i < 4; i++)
                #pragma unroll
                for (int j = 0; j < 8; j++) mma_tf32(acc[i][j], afr[i], bfr[j]);
        }
        __syncthreads();
    }

    const float s = rsqrtf(scal[0] * scal[1]);   // 1/(||q||*||k||)
    #pragma unroll
    for (int j = 0; j < 8; j++) {
        int c = n0 + warp_n + j * 8 + tig * 2;
        #pragma unroll
        for (int i = 0; i < 4; i++) {
            int r = m0 + warp_m + i * 16 + gid;
            float iv0 = invp[2 * (size_t)r];
            float iv1 = invp[2 * (size_t)(r + 8)];
            float2 va  = *(const float2*)(Vb + (size_t)r * 1024 + c);
            float2 vbv = *(const float2*)(Vb + (size_t)(r + 8) * 1024 + c);
            float x0 = (acc[i][j][0] * s + 65536.f * va.x)  * iv0 * 0.5f;
            float x1 = (acc[i][j][1] * s + 65536.f * va.y)  * iv0 * 0.5f;
            float x2 = (acc[i][j][2] * s + 65536.f * vbv.x) * iv1 * 0.5f;
            float x3 = (acc[i][j][3] * s + 65536.f * vbv.y) * iv1 * 0.5f;
            float* c0 = C + (size_t)r * 1024 + c;
            float* c1 = C + (size_t)(r + 8) * 1024 + c;
            if (beta) {
                float2 o0 = *(float2*)c0, o1 = *(float2*)c1;
                x0 += o0.x; x1 += o0.y; x2 += o1.x; x3 += o1.y;
            }
            *(float2*)c0 = make_float2(x0, x1);
            *(float2*)c1 = make_float2(x2, x3);
        }
    }
}

// ---------------------------------------------------------------------------
// TN GEMM for kvs (v2 core): C[m,d] = sum_l K[l,m]*V[l,d], split-K partials.
// ---------------------------------------------------------------------------
__global__ __launch_bounds__(256) void gemm_tn_kv_v2(
    const float* __restrict__ Kp, const float* __restrict__ Vp,
    float* __restrict__ part)
{
    __shared__ unsigned As[16][264];   // [l][m]
    __shared__ unsigned Bs[16][264];   // [l][d]

    const int tid = threadIdx.x;
    const int lane = tid & 31;
    const int wid = tid >> 5;
    const int gid = lane >> 2, tig = lane & 3;
    const int warp_m = (wid & 1) * 64;
    const int warp_n = (wid >> 1) * 64;
    const int d0 = blockIdx.x * 256;
    const int m0 = blockIdx.y * 128;
    const int h  = blockIdx.z >> 4;
    const int sp = blockIdx.z & 15;
    const int CH = NPTS / KVSPL;       // 4096

    const float* Ab = Kp + (size_t)h * 512;
    const float* Bb = Vp + (size_t)h * 512;

    float acc[4][8][4];
    #pragma unroll
    for (int i = 0; i < 4; i++)
        #pragma unroll
        for (int j = 0; j < 8; j++)
            #pragma unroll
            for (int r = 0; r < 4; r++) acc[i][j][r] = 0.f;

    const int lbeg = sp * CH, lend = lbeg + CH;

    float4 pa[2], pb[4];
    #pragma unroll
    for (int it = 0; it < 2; it++) {
        int idx = tid + it * 256;
        int lrow = idx >> 5, mcol4 = (idx & 31) << 2;
        pa[it] = *(const float4*)(Ab + (size_t)(lbeg + lrow) * 1024 + m0 + mcol4);
    }
    #pragma unroll
    for (int it = 0; it < 4; it++) {
        int idx = tid + it * 256;
        int lrow = idx >> 6, dcol4 = (idx & 63) << 2;
        pb[it] = *(const float4*)(Bb + (size_t)(lbeg + lrow) * 1024 + d0 + dcol4);
    }

    for (int l0 = lbeg; l0 < lend; l0 += 16) {
        #pragma unroll
        for (int it = 0; it < 2; it++) {
            int idx = tid + it * 256;
            int lrow = idx >> 5, mcol4 = (idx & 31) << 2;
            *(uint4*)&As[lrow][mcol4] = make_uint4(
                tf32_of(pa[it].x), tf32_of(pa[it].y),
                tf32_of(pa[it].z), tf32_of(pa[it].w));
        }
        #pragma unroll
        for (int it = 0; it < 4; it++) {
            int idx = tid + it * 256;
            int lrow = idx >> 6, dcol4 = (idx & 63) << 2;
            *(uint4*)&Bs[lrow][dcol4] = make_uint4(
                tf32_of(pb[it].x), tf32_of(pb[it].y),
                tf32_of(pb[it].z), tf32_of(pb[it].w));
        }
        __syncthreads();

        if (l0 + 16 < lend) {
            #pragma unroll
            for (int it = 0; it < 2; it++) {
                int idx = tid + it * 256;
                int lrow = idx >> 5, mcol4 = (idx & 31) << 2;
                pa[it] = *(const float4*)(Ab + (size_t)(l0 + 16 + lrow) * 1024 + m0 + mcol4);
            }
            #pragma unroll
            for (int it = 0; it < 4; it++) {
                int idx = tid + it * 256;
                int lrow = idx >> 6, dcol4 = (idx & 63) << 2;
                pb[it] = *(const float4*)(Bb + (size_t)(l0 + 16 + lrow) * 1024 + d0 + dcol4);
            }
        }

        #pragma unroll
        for (int kk = 0; kk < 16; kk += 8) {
            unsigned afr[4][4], bfr[8][2];
            #pragma unroll
            for (int i = 0; i < 4; i++) {
                int mm = warp_m + i * 16 + gid;
                afr[i][0] = As[kk + tig][mm];
                afr[i][1] = As[kk + tig][mm + 8];
                afr[i][2] = As[kk + tig + 4][mm];
                afr[i][3] = As[kk + tig + 4][mm + 8];
            }
            #pragma unroll
            for (int j = 0; j < 8; j++) {
                int nn = warp_n + j * 8 + gid;
                bfr[j][0] = Bs[kk + tig][nn];
                bfr[j][1] = Bs[kk + tig + 4][nn];
            }
            #pragma unroll
            for (int i = 0; i < 4; i++)
                #pragma unroll
                for (int j = 0; j < 8; j++) mma_tf32(acc[i][j], afr[i], bfr[j]);
        }
        __syncthreads();
    }

    float* P = part + (size_t)blockIdx.z * 262144u;
    #pragma unroll
    for (int j = 0; j < 8; j++) {
        int c = d0 + warp_n + j * 8 + tig * 2;
        #pragma unroll
        for (int i = 0; i < 4; i++) {
            int r = m0 + warp_m + i * 16 + gid;
            *(float2*)(P + (size_t)r * 512 + c)       = make_float2(acc[i][j][0], acc[i][j][1]);
            *(float2*)(P + (size_t)(r + 8) * 512 + c) = make_float2(acc[i][j][2], acc[i][j][3]);
        }
    }
}

__global__ void kv_reduce(const float* __restrict__ part, float* __restrict__ kvs) {
    int idx = blockIdx.x * 256 + threadIdx.x;          // 0..524287
    int h = idx >> 18;
    int i = idx & 262143;
    const float* p = part + (size_t)(h * KVSPL) * 262144u + i;
    float s = 0.f;
    #pragma unroll
    for (int sp = 0; sp < KVSPL; sp++) s += p[(size_t)sp * 262144u];
    kvs[idx] = s;
}

// ---------------------------------------------------------------------------
// Deterministic scalar reduce of n partials
// ---------------------------------------------------------------------------
__global__ __launch_bounds__(256) void reduce_to_scalar(
    const float* __restrict__ part, int n, float* __restrict__ out)
{
    __shared__ float sm[8];
    float s = 0.f;
    for (int i = threadIdx.x; i < n; i += 256) s += part[i];
    s = block_reduce_sum(s, sm);
    if (threadIdx.x == 0) *out = s;
}

// ---------------------------------------------------------------------------
// ks[col] = sum over 512 per-block partials (from K-proj epilogue)
// ---------------------------------------------------------------------------
__global__ __launch_bounds__(256) void ks_reduce512(
    const float* __restrict__ ksp, float* __restrict__ out)
{
    int col = blockIdx.x * 256 + threadIdx.x;   // grid = 4
    float s = 0.f;
    for (int by = 0; by < 512; by++) s += ksp[(size_t)by * 1024 + col];
    out[col] = s;
}

// ---------------------------------------------------------------------------
// inv from qdp partials: inv[2n+h] = 1/( (qdp sums)*s + 65536 )
// ---------------------------------------------------------------------------
__global__ __launch_bounds__(256) void inv_from_qdp(
    const float* __restrict__ qdp, const float* __restrict__ scal,
    float* __restrict__ inv)
{
    int n = blockIdx.x * 256 + threadIdx.x;     // grid = 256
    float s = rsqrtf(scal[0] * scal[1]);
    float qd0 = qdp[n] + qdp[65536u + n];
    float qd1 = qdp[2u * 65536u + n] + qdp[3u * 65536u + n];
    inv[2 * n]     = 1.0f / (qd0 * s + 65536.0f);
    inv[2 * n + 1] = 1.0f / (qd1 * s + 65536.0f);
}

// ---------------------------------------------------------------------------
// fc0 epilogue: LayerNorm + ReLU, one block per row
// ---------------------------------------------------------------------------
__global__ __launch_bounds__(256) void ln_relu(
    const float* __restrict__ x, const float* __restrict__ g,
    const float* __restrict__ b, float* __restrict__ out)
{
    __shared__ float sm[8];
    int n = blockIdx.x, t = threadIdx.x;
    size_t r = (size_t)n * 512;
    float v0 = x[r + t], v1 = x[r + 256 + t];
    float mu = block_reduce_sum(v0 + v1, sm) * (1.f / 512.f);
    float d0 = v0 - mu, d1 = v1 - mu;
    float var = block_reduce_sum(d0 * d0 + d1 * d1, sm) * (1.f / 512.f);
    float rs = rsqrtf(var + 1e-5f);
    float o0 = d0 * rs * g[t] + b[t];
    float o1 = d1 * rs * g[t + 256] + b[t + 256];
    out[r + t]       = fmaxf(o0, 0.f);
    out[r + 256 + t] = fmaxf(o1, 0.f);
}

// ---------------------------------------------------------------------------
// Residual + LayerNorm: out = LN(0.5*attn + 0.5*prev). attn has ld 1024.
// ---------------------------------------------------------------------------
__global__ __launch_bounds__(256) void combine_res_ln(
    const float* __restrict__ attn, const float* __restrict__ prev,
    const float* __restrict__ g, const float* __restrict__ b,
    float* __restrict__ out)
{
    __shared__ float sm[8];
    int n = blockIdx.x, t = threadIdx.x;
    size_t r1 = (size_t)n * 1024;
    size_t r5 = (size_t)n * 512;
    float val0 = 0.5f * attn[r1 + t]       + 0.5f * prev[r5 + t];
    float val1 = 0.5f * attn[r1 + 256 + t] + 0.5f * prev[r5 + 256 + t];
    float mu = block_reduce_sum(val0 + val1, sm) * (1.f / 512.f);
    float d0 = val0 - mu, d1 = val1 - mu;
    float var = block_reduce_sum(d0 * d0 + d1 * d1, sm) * (1.f / 512.f);
    float rs = rsqrtf(var + 1e-5f);
    out[r5 + t]       = d0 * rs * g[t] + b[t];
    out[r5 + 256 + t] = d1 * rs * g[t + 256] + b[t + 256];
}

// ---------------------------------------------------------------------------
// Launch
// ---------------------------------------------------------------------------
extern "C" void kernel_launch(void* const* d_in, const int* in_sizes, int n_in,
                              void* d_out, int out_size)
{
    (void)in_sizes; (void)n_in; (void)out_size;
    const float* x     = (const float*)d_in[0];
    const float* fc0_w = (const float*)d_in[1];
    const float* fc0_b = (const float*)d_in[2];
    const float* ln0_g = (const float*)d_in[3];
    const float* ln0_b = (const float*)d_in[4];
    const float* wq    = (const float*)d_in[5];
    const float* bq    = (const float*)d_in[6];
    const float* wk    = (const float*)d_in[7];
    const float* bk    = (const float*)d_in[8];
    const float* wv    = (const float*)d_in[9];
    const float* bv    = (const float*)d_in[10];
    const float* lng   = (const float*)d_in[11];
    const float* lnb   = (const float*)d_in[12];
    float* out = (float*)d_out;

    float *qk, *v, *hbuf, *kvp, *kvs, *ksp, *ks, *red, *scal, *qdp, *inv;
    cudaGetSymbolAddress((void**)&qk,   g_qk);
    cudaGetSymbolAddress((void**)&v,    g_v);
    cudaGetSymbolAddress((void**)&hbuf, g_h);
    cudaGetSymbolAddress((void**)&kvp,  g_kvp);
    cudaGetSymbolAddress((void**)&kvs,  g_kvs);
    cudaGetSymbolAddress((void**)&ksp,  g_ksp);
    cudaGetSymbolAddress((void**)&ks,   g_ks);
    cudaGetSymbolAddress((void**)&red,  g_red);
    cudaGetSymbolAddress((void**)&scal, g_scal);
    cudaGetSymbolAddress((void**)&qdp,  g_qdp);
    cudaGetSymbolAddress((void**)&inv,  g_inv);

    dim3 thr(256);

    // --- input projection: h = relu(LN(x @ fc0_w + fc0_b)) ---
    gemm_nn_v2<<<dim3(2, 512), thr>>>(x, fc0_w, fc0_b, v,
                                      NPTS, 512, 512, 512, 512, 512,
                                      nullptr, nullptr, nullptr, nullptr);
    ln_relu<<<NPTS, thr>>>(v, ln0_g, ln0_b, hbuf);

    for (int L = 0; L < 2; L++) {
        const float* prev = L ? out : hbuf;
        float* lout = out;                       // layer 1 in-place (row-local)
        const float* WQ  = wq + (size_t)L * 512 * 1024;
        const float* WK  = wk + (size_t)L * 512 * 1024;
        const float* WV  = wv + (size_t)L * 512 * 1024;
        const float* BQ  = bq + (size_t)L * 1024;
        const float* BKb = bk + (size_t)L * 1024;
        const float* BV  = bv + (size_t)L * 1024;

        // V projection
        gemm_nn_v2<<<dim3(4, 512), thr>>>(prev, WV, BV, v,
                                          NPTS, HH, HID, 512, 1024, 1024,
                                          nullptr, nullptr, nullptr, nullptr);
        // K projection (+ sum-of-squares partials, + column-sum partials)
        gemm_nn_v2<<<dim3(4, 512), thr>>>(prev, WK, BKb, qk,
                                          NPTS, HH, HID, 512, 1024, 1024,
                                          red + 4096, ksp, nullptr, nullptr);
        reduce_to_scalar<<<1, thr>>>(red + 4096, 2048, scal + 1);
        ks_reduce512<<<4, thr>>>(ksp, ks);

        // kvs = K^T V per head (split-K, deterministic)
        gemm_tn_kv_v2<<<dim3(2, 4, 32), thr>>>(qk, v, kvp);
        kv_reduce<<<2048, thr>>>(kvp, kvs);

        // Q projection overwrites K (K dead) (+ ss partials, + q.ks partials)
        gemm_nn_v2<<<dim3(4, 512), thr>>>(prev, WQ, BQ, qk,
                                          NPTS, HH, HID, 512, 1024, 1024,
                                          red, nullptr, ks, qdp);
        reduce_to_scalar<<<1, thr>>>(red, 2048, scal + 0);

        // per-row denominators from fused partials
        inv_from_qdp<<<256, thr>>>(qdp, scal, inv);

        // fused Q@kvs + attention combine; attn aliases V's head-0 half
        gemm_attn_v2<<<dim3(2, 512), thr>>>(qk, kvs, v, inv, scal, v, 0);
        gemm_attn_v2<<<dim3(2, 512), thr>>>(qk + 512, kvs + 262144u,
                                            v + 512, inv + 1, scal, v, 1);

        // residual + LN
        combine_res_ln<<<NPTS, thr>>>(v, prev,
                                      lng + (size_t)L * 512, lnb + (size_t)L * 512,
                                      lout);
    }
}